// round 14
// baseline (speedup 1.0000x reference)
#include <cuda_runtime.h>
#include <cuda_fp16.h>
#include <stdint.h>

// ===========================================================================
// GCN forward, fp16 mma.sync (fp32 accum), reassociated to minimize MACs:
//   T1: P1[b]   = adj[b] @ x[b]            (M=1024,N=512, K=1024) x64
//   T2: h1      = relu(P1 @ W1 + b1)       (M=65536,N=1024,K=512)
//   T3: S2^T    = W2^T @ h1^T              (M=512,N=65536,K=1024)  [SWAP grid]
//   T4: pool[b]+= mask.(relu(adj[b]@S2[b]+b2) . Wl)   (rows >= len skipped)
//   out[b] = pool[b]/len[b] + bl
// R12: warp tile 64x64 with 4 warps/CTA (2x2), CTA tile 128x128, still
// 2 CTAs/SM. Halves ldmatrix A/B re-read redundancy -> smem crossbar load
// drops from ~128 B/cyc (saturated) to ~96 B/cyc at full tensor rate.
// ===========================================================================

#define BM 128
#define BN 128
#define BK 64                       // fp16 per chunk (=128B per row)
#define NSTG 3
#define NTHR 128

#define A_BYTES (BM * 128)          // 16384
#define B_BYTES (BN * 128)          // 16384
#define STG     (A_BYTES + B_BYTES) // 32768
#define SMEM_TOTAL (NSTG * STG)     // 98304

#define SWZ(off) ((off) ^ (((off) >> 3) & 0x70))

__device__ __forceinline__ uint32_t smem_u32(const void* p) {
    uint32_t a;
    asm("{ .reg .u64 t; cvta.to.shared.u64 t, %1; cvt.u32.u64 %0, t; }" : "=r"(a) : "l"(p));
    return a;
}
__device__ __forceinline__ void cp16(uint32_t dst, const void* src) {
    asm volatile("cp.async.cg.shared.global [%0], [%1], 16;" :: "r"(dst), "l"(src));
}
#define CP_COMMIT() asm volatile("cp.async.commit_group;" ::: "memory")
#define CP_WAIT(n)  asm volatile("cp.async.wait_group %0;" :: "n"(n) : "memory")

__device__ __forceinline__ void ldsm4(uint32_t* r, uint32_t addr) {
    asm volatile("ldmatrix.sync.aligned.m8n8.x4.shared.b16 {%0,%1,%2,%3}, [%4];"
                 : "=r"(r[0]), "=r"(r[1]), "=r"(r[2]), "=r"(r[3]) : "r"(addr));
}
__device__ __forceinline__ void mma_fp16(float* d, const uint32_t* a, const uint32_t* b) {
    asm volatile("mma.sync.aligned.m16n8k16.row.col.f32.f16.f16.f32 "
                 "{%0,%1,%2,%3}, {%4,%5,%6,%7}, {%8,%9}, {%0,%1,%2,%3};"
                 : "+f"(d[0]), "+f"(d[1]), "+f"(d[2]), "+f"(d[3])
                 : "r"(a[0]), "r"(a[1]), "r"(a[2]), "r"(a[3]), "r"(b[0]), "r"(b[1]));
}
__device__ __forceinline__ uint32_t pack2h(float a, float b) {
    __half2 t = __floats2half2_rn(a, b);
    return *(uint32_t*)&t;
}

// ---------------------------------------------------------------------------
// Static device scratch
// ---------------------------------------------------------------------------
__device__ __half g_Jh[64u * 1024u * 1024u];    // adj fp16
__device__ __half g_XT[64u * 512u * 1024u];     // x^T per batch [b][f][n]
__device__ __half g_W1T[1024u * 512u];          // W1^T [h1][f]
__device__ __half g_W2T[512u * 1024u];          // W2^T [h2][h1]
__device__ __half g_P1[65536u * 512u];          // adj@x  [n][f]
__device__ __half g_H1[65536u * 1024u];         // h1 [n][h1]
__device__ __half g_S2T[512u * 65536u];         // support2^T [h2][b*1024+n]
__device__ float  g_pool[64];

// ---------------------------------------------------------------------------
// fp32 -> fp16 elementwise convert; block 0 also zeroes the pool accumulator.
// ---------------------------------------------------------------------------
__global__ void __launch_bounds__(256)
convert_kernel(const float* __restrict__ src, __half* __restrict__ dst, size_t n4,
               float* __restrict__ pool)
{
    if (pool != nullptr && blockIdx.x == 0 && threadIdx.x < 64)
        pool[threadIdx.x] = 0.0f;
    size_t stride = (size_t)gridDim.x * blockDim.x;
    for (size_t i = (size_t)blockIdx.x * blockDim.x + threadIdx.x; i < n4; i += stride) {
        float4 v = ((const float4*)src)[i];
        uint2 o;
        o.x = pack2h(v.x, v.y);
        o.y = pack2h(v.z, v.w);
        ((uint2*)dst)[i] = o;
    }
}

// ---------------------------------------------------------------------------
// Tiled transpose-convert: src[z][R][C] fp32 -> dst[z][C][R] fp16.
// 64(rows) x 32(cols) tiles; 128B-coalesced __half2 stores (R11-verified).
// ---------------------------------------------------------------------------
__global__ void __launch_bounds__(256)
trans_kernel(const float* __restrict__ src, __half* __restrict__ dst, int R, int C)
{
    __shared__ float tile[64][33];
    const size_t zoff = (size_t)blockIdx.z * R * C;
    const int r0 = blockIdx.y * 64;
    const int c0 = blockIdx.x * 32;
    const int tx = threadIdx.x & 31;
    const int ty = threadIdx.x >> 5;            // warp id 0..7

    const float* s = src + zoff + (size_t)r0 * C + c0;
    #pragma unroll
    for (int i = ty; i < 64; i += 8) tile[i][tx] = s[(size_t)i * C + tx];
    __syncthreads();

    __half* d = dst + zoff;
    #pragma unroll
    for (int j = 0; j < 4; j++) {
        const int c = ty + j * 8;               // column handled by this warp
        __half2 v = __floats2half2_rn(tile[2 * tx][c], tile[2 * tx + 1][c]);
        *(__half2*)(d + (size_t)(c0 + c) * R + r0 + 2 * tx) = v;
    }
}

// ---------------------------------------------------------------------------
// mma.sync fp16 GEMM: D[128,128] per CTA, 4 warps (2x2), warp tile 64x64.
// EPI: 0 = fp16 out; 1 = bias+ReLU fp16 out; 3 = bias+ReLU+masked pool.Wl.
// SWAP: blockIdx.x indexes M (keeps co-scheduled CTAs on the same B rows).
// ---------------------------------------------------------------------------
template <int EPI, bool SWAP>
__global__ void __launch_bounds__(NTHR, 2)
mma_gemm(const __half* __restrict__ Ag, int lda, size_t strA,
         const __half* __restrict__ Bg, int ldb, size_t strB,
         const float* __restrict__ bias,
         __half* __restrict__ Ch, int ldc, size_t strC,
         const float* __restrict__ Wl, const int* __restrict__ length,
         float* __restrict__ pool,
         int nch)
{
    extern __shared__ char smem[];
    const int bz = blockIdx.z;
    const int m0 = (SWAP ? blockIdx.x : blockIdx.y) * BM;
    const int n0 = (SWAP ? blockIdx.y : blockIdx.x) * BN;

    int len = 0;
    if (EPI == 3) {
        len = length[bz];
        if (m0 >= len) return;
    }

    const uint32_t sb = smem_u32(smem);
    const int tid = threadIdx.x;
    const int wid = tid >> 5;       // 0..3
    const int l   = tid & 31;
    const int warp_m = wid & 1;     // 2 x 64 rows
    const int warp_n = wid >> 1;    // 2 x 64 cols

    const __half* pA = Ag + strA * bz;
    const __half* pB = Bg + strB * bz;

    const int ld_row = tid >> 3;    // 0..15
    const int ld_c16 = tid & 7;

    auto load_tiles = [&](int c, int st) {
        const int kbase = c * BK;
        const uint32_t sbase = sb + st * STG;
        #pragma unroll
        for (int it = 0; it < 8; it++) {          // A: 128 rows, 16 rows/iter
            const int row = ld_row + it * 16;
            cp16(sbase + SWZ((uint32_t)(row * 128 + ld_c16 * 16)),
                 pA + (size_t)(m0 + row) * lda + kbase + ld_c16 * 8);
        }
        #pragma unroll
        for (int it = 0; it < 8; it++) {          // B: 128 rows
            const int row = ld_row + it * 16;
            cp16(sbase + A_BYTES + SWZ((uint32_t)(row * 128 + ld_c16 * 16)),
                 pB + (size_t)(n0 + row) * ldb + kbase + ld_c16 * 8);
        }
    };

    const int a_row_l = l & 15;
    const uint32_t a_koff = (uint32_t)((l >> 4) * 16);
    const int b_row_l = (l & 7) + ((l >> 4) * 8);
    const uint32_t b_koff = (uint32_t)(((l >> 3) & 1) * 16);

    uint32_t a_rb[4], b_rb[4];
    #pragma unroll
    for (int mi = 0; mi < 4; mi++)
        a_rb[mi] = (uint32_t)((warp_m * 64 + mi * 16 + a_row_l) * 128);
    #pragma unroll
    for (int nb = 0; nb < 4; nb++)
        b_rb[nb] = (uint32_t)((warp_n * 64 + nb * 16 + b_row_l) * 128);

    float acc[4][8][4];
    #pragma unroll
    for (int mi = 0; mi < 4; mi++)
        #pragma unroll
        for (int ni = 0; ni < 8; ni++)
            #pragma unroll
            for (int q = 0; q < 4; q++) acc[mi][ni][q] = 0.0f;

    load_tiles(0, 0);
    CP_COMMIT();
    if (1 < nch) { load_tiles(1, 1); CP_COMMIT(); }

    for (int c = 0; c < nch; c++) {
        if (c + 1 < nch) { CP_WAIT(1); } else { CP_WAIT(0); }
        __syncthreads();
        // Safe without a trailing barrier: stage (c+2)%3 == (c-1)%3, and every
        // warp consumed stage c-1 before it could reach the barrier above.
        if (c + 2 < nch) {
            load_tiles(c + 2, (c + 2) % NSTG);
            CP_COMMIT();
        }

        const uint32_t sA = sb + (c % NSTG) * STG;
        const uint32_t sB = sA + A_BYTES;

        #pragma unroll
        for (int ks = 0; ks < 4; ks++) {
            const uint32_t kb = (uint32_t)(ks * 32);
            uint32_t Ah[4][4], Bh[4][4];
            #pragma unroll
            for (int mi = 0; mi < 4; mi++)
                ldsm4(Ah[mi], sA + SWZ(a_rb[mi] + kb + a_koff));
            #pragma unroll
            for (int nb = 0; nb < 4; nb++)
                ldsm4(Bh[nb], sB + SWZ(b_rb[nb] + kb + b_koff));
            #pragma unroll
            for (int mi = 0; mi < 4; mi++)
                #pragma unroll
                for (int ni = 0; ni < 8; ni++)
                    mma_fp16(acc[mi][ni], Ah[mi], &Bh[ni >> 1][(ni & 1) * 2]);
        }
    }

    // ---- epilogue ----
    const int er = warp_m * 64 + (l >> 2);
    const int ec = warp_n * 64 + 2 * (l & 3);

    if (EPI <= 1) {
        #pragma unroll
        for (int mi = 0; mi < 4; mi++) {
            const int row = m0 + er + mi * 16;
            const size_t ro0 = strC * bz + (size_t)row * ldc;
            const size_t ro1 = ro0 + (size_t)8 * ldc;
            #pragma unroll
            for (int ni = 0; ni < 8; ni++) {
                const int col = n0 + ec + ni * 8;
                float v00 = acc[mi][ni][0], v01 = acc[mi][ni][1];
                float v10 = acc[mi][ni][2], v11 = acc[mi][ni][3];
                if (EPI == 1) {
                    const float2 bb = *(const float2*)(bias + col);
                    v00 = fmaxf(v00 + bb.x, 0.0f);
                    v01 = fmaxf(v01 + bb.y, 0.0f);
                    v10 = fmaxf(v10 + bb.x, 0.0f);
                    v11 = fmaxf(v11 + bb.y, 0.0f);
                }
                *(uint32_t*)(Ch + ro0 + col) = pack2h(v00, v01);
                *(uint32_t*)(Ch + ro1 + col) = pack2h(v10, v11);
            }
        }
    } else {
        // EPI==3: bias + ReLU + masked dot with Wl, reduce, atomicAdd per batch
        float part = 0.0f;
        #pragma unroll
        for (int mi = 0; mi < 4; mi++) {
            const int grow0 = m0 + er + mi * 16;
            const bool k0 = grow0 < len;
            const bool k1 = grow0 + 8 < len;
            #pragma unroll
            for (int ni = 0; ni < 8; ni++) {
                const int col = n0 + ec + ni * 8;
                const float2 bb = *(const float2*)(bias + col);
                const float2 wl = *(const float2*)(Wl + col);
                float v00 = fmaxf(acc[mi][ni][0] + bb.x, 0.0f);
                float v01 = fmaxf(acc[mi][ni][1] + bb.y, 0.0f);
                float v10 = fmaxf(acc[mi][ni][2] + bb.x, 0.0f);
                float v11 = fmaxf(acc[mi][ni][3] + bb.y, 0.0f);
                if (k0) part += v00 * wl.x + v01 * wl.y;
                if (k1) part += v10 * wl.x + v11 * wl.y;
            }
        }
        #pragma unroll
        for (int o = 16; o > 0; o >>= 1)
            part += __shfl_xor_sync(0xFFFFFFFFu, part, o);
        __syncthreads();
        float* red = (float*)smem;
        if (l == 0) red[wid] = part;
        __syncthreads();
        if (tid == 0) {
            float s = 0.0f;
            #pragma unroll
            for (int i = 0; i < 4; i++) s += red[i];
            atomicAdd(pool + bz, s);
        }
    }
}

// ---------------------------------------------------------------------------
__global__ void final_kernel(const float* __restrict__ pool,
                             const int* __restrict__ length,
                             const float* __restrict__ bl,
                             float* __restrict__ out)
{
    const int b = threadIdx.x;
    out[b] = pool[b] / (float)length[b] + bl[0];
}

// ---------------------------------------------------------------------------
extern "C" void kernel_launch(void* const* d_in, const int* in_sizes, int n_in,
                              void* d_out, int out_size)
{
    const float* x      = (const float*)d_in[0];
    const float* adj    = (const float*)d_in[1];
    const int*   length = (const int*)  d_in[2];
    const float* W1     = (const float*)d_in[3];
    const float* b1     = (const float*)d_in[4];
    const float* W2     = (const float*)d_in[5];
    const float* b2     = (const float*)d_in[6];
    const float* Wl     = (const float*)d_in[7];
    const float* bl     = (const float*)d_in[8];
    float* out = (float*)d_out;

    __half *Jh, *XT, *W1T, *W2T, *P1, *H1, *S2T;
    float* pool;
    cudaGetSymbolAddress((void**)&Jh,  g_Jh);
    cudaGetSymbolAddress((void**)&XT,  g_XT);
    cudaGetSymbolAddress((void**)&W1T, g_W1T);
    cudaGetSymbolAddress((void**)&W2T, g_W2T);
    cudaGetSymbolAddress((void**)&P1,  g_P1);
    cudaGetSymbolAddress((void**)&H1,  g_H1);
    cudaGetSymbolAddress((void**)&S2T, g_S2T);
    cudaGetSymbolAddress((void**)&pool, g_pool);

    cudaFuncSetAttribute(mma_gemm<0, false>, cudaFuncAttributeMaxDynamicSharedMemorySize, SMEM_TOTAL);
    cudaFuncSetAttribute(mma_gemm<1, false>, cudaFuncAttributeMaxDynamicSharedMemorySize, SMEM_TOTAL);
    cudaFuncSetAttribute(mma_gemm<0, true>,  cudaFuncAttributeMaxDynamicSharedMemorySize, SMEM_TOTAL);
    cudaFuncSetAttribute(mma_gemm<3, false>, cudaFuncAttributeMaxDynamicSharedMemorySize, SMEM_TOTAL);

    // converts (adj convert also zeroes the pool accumulator)
    convert_kernel<<<8192, 256>>>(adj, Jh, (size_t)64 * 1024 * 1024 / 4, pool);
    trans_kernel<<<dim3(16, 16, 64), 256>>>(x,  XT,  1024, 512);   // x^T per batch
    trans_kernel<<<dim3(32, 8,  1),  256>>>(W1, W1T, 512, 1024);   // W1^T
    trans_kernel<<<dim3(16, 16, 1),  256>>>(W2, W2T, 1024, 512);   // W2^T

    // T1: P1[b] = adj[b] @ x[b]   (M=1024, N=512, K=1024) x64
    mma_gemm<0, false><<<dim3(4, 8, 64), NTHR, SMEM_TOTAL>>>(
        Jh, 1024, (size_t)1024 * 1024,
        XT, 1024, (size_t)512 * 1024,
        nullptr, P1, 512, (size_t)1024 * 512,
        nullptr, nullptr, nullptr, 1024 / BK);

    // T2: h1 = relu(P1 @ W1 + b1)  (M=65536, N=1024, K=512)
    mma_gemm<1, false><<<dim3(8, 512, 1), NTHR, SMEM_TOTAL>>>(
        P1, 512, 0,
        W1T, 512, 0,
        b1, H1, 1024, 0,
        nullptr, nullptr, nullptr, 512 / BK);

    // T3: S2^T = W2^T @ h1^T  (M=512, N=65536, K=1024), SWAP grid so the
    // co-scheduled M-blocks share each h1 row-group through L2.
    mma_gemm<0, true><<<dim3(4, 512, 1), NTHR, SMEM_TOTAL>>>(
        W2T, 1024, 0,
        H1, 1024, 0,
        nullptr, S2T, 65536, 0,
        nullptr, nullptr, nullptr, 1024 / BK);

    // T4: fused relu(adj[b]@S2[b]+b2) . Wl with row mask, row-block skip
    mma_gemm<3, false><<<dim3(4, 8, 64), NTHR, SMEM_TOTAL>>>(
        Jh, 1024, (size_t)1024 * 1024,
        S2T, 65536, 1024,
        b2, nullptr, 0, 0,
        Wl, length, pool, 1024 / BK);

    final_kernel<<<1, 64>>>(pool, length, bl, out);

    (void)in_sizes; (void)n_in; (void)out_size;
}

// round 17
// speedup vs baseline: 1.0152x; 1.0152x over previous
#include <cuda_runtime.h>
#include <cuda_fp16.h>
#include <stdint.h>

// ===========================================================================
// GCN forward, fp16 mma.sync (fp32 accum), reassociated to minimize MACs:
//   T1: P1[b]   = adj[b] @ x[b]            (M=1024,N=512, K=1024) x64
//   T2: h1      = relu(P1 @ W1 + b1)       (M=65536,N=1024,K=512)
//   T3: S2^T    = W2^T @ h1^T              (M=512,N=65536,K=1024)  [SWAP grid]
//   T4: pool[b]+= mask.(relu(adj[b]@S2[b]+b2) . Wl)   (rows >= len skipped)
//   out[b] = pool[b]/len[b] + bl
// R13: GEMM = best measured config (R11: 128x128, 8 warps, 2 CTAs/SM, NSTG=3;
// all structural variants measured flat -> at the mma.sync rate ceiling).
// All prep (adj convert + x transpose + W transposes + pool zero) merged into
// ONE kernel launch with block-range dispatch so the small transposes overlap
// the big convert instead of serializing after it.
// ===========================================================================

#define BM 128
#define BN 128
#define BK 64                       // fp16 per chunk (=128B per row)
#define NSTG 3

#define A_BYTES (BM * 128)          // 16384
#define B_BYTES (BN * 128)          // 16384
#define STG     (A_BYTES + B_BYTES) // 32768
#define SMEM_TOTAL (NSTG * STG)     // 98304

#define SWZ(off) ((off) ^ (((off) >> 3) & 0x70))

// prep grid partition
#define PREP_CVT_BLKS   8192        // adj fp32->fp16 grid-stride
#define PREP_XT_BLKS    16384       // x transpose: 16 ctiles x 16 rtiles x 64
#define PREP_W1_BLKS    256         // W1: 32 ctiles x 8 rtiles
#define PREP_W2_BLKS    256         // W2: 16 ctiles x 16 rtiles
#define PREP_TOTAL (PREP_CVT_BLKS + PREP_XT_BLKS + PREP_W1_BLKS + PREP_W2_BLKS)

__device__ __forceinline__ uint32_t smem_u32(const void* p) {
    uint32_t a;
    asm("{ .reg .u64 t; cvta.to.shared.u64 t, %1; cvt.u32.u64 %0, t; }" : "=r"(a) : "l"(p));
    return a;
}
__device__ __forceinline__ void cp16(uint32_t dst, const void* src) {
    asm volatile("cp.async.cg.shared.global [%0], [%1], 16;" :: "r"(dst), "l"(src));
}
#define CP_COMMIT() asm volatile("cp.async.commit_group;" ::: "memory")
#define CP_WAIT(n)  asm volatile("cp.async.wait_group %0;" :: "n"(n) : "memory")

__device__ __forceinline__ void ldsm4(uint32_t* r, uint32_t addr) {
    asm volatile("ldmatrix.sync.aligned.m8n8.x4.shared.b16 {%0,%1,%2,%3}, [%4];"
                 : "=r"(r[0]), "=r"(r[1]), "=r"(r[2]), "=r"(r[3]) : "r"(addr));
}
__device__ __forceinline__ void mma_fp16(float* d, const uint32_t* a, const uint32_t* b) {
    asm volatile("mma.sync.aligned.m16n8k16.row.col.f32.f16.f16.f32 "
                 "{%0,%1,%2,%3}, {%4,%5,%6,%7}, {%8,%9}, {%0,%1,%2,%3};"
                 : "+f"(d[0]), "+f"(d[1]), "+f"(d[2]), "+f"(d[3])
                 : "r"(a[0]), "r"(a[1]), "r"(a[2]), "r"(a[3]), "r"(b[0]), "r"(b[1]));
}
__device__ __forceinline__ uint32_t pack2h(float a, float b) {
    __half2 t = __floats2half2_rn(a, b);
    return *(uint32_t*)&t;
}

// ---------------------------------------------------------------------------
// Static device scratch
// ---------------------------------------------------------------------------
__device__ __half g_Jh[64u * 1024u * 1024u];    // adj fp16
__device__ __half g_XT[64u * 512u * 1024u];     // x^T per batch [b][f][n]
__device__ __half g_W1T[1024u * 512u];          // W1^T [h1][f]
__device__ __half g_W2T[512u * 1024u];          // W2^T [h2][h1]
__device__ __half g_P1[65536u * 512u];          // adj@x  [n][f]
__device__ __half g_H1[65536u * 1024u];         // h1 [n][h1]
__device__ __half g_S2T[512u * 65536u];         // support2^T [h2][b*1024+n]
__device__ float  g_pool[64];

// ---------------------------------------------------------------------------
// Unified prep kernel: block-range dispatch.
//   [0, 8192)           adj fp32 -> fp16 (grid-stride float4)  + pool zero
//   [8192, 24576)       x[b,n,f] -> xT[b,f,n]   (64x32 transpose tiles)
//   [24576, 24832)      W1[512,1024] -> W1T
//   [24832, 25088)      W2[1024,512] -> W2T
// ---------------------------------------------------------------------------
__device__ __forceinline__ void trans_tile(const float* __restrict__ src,
                                           __half* __restrict__ dst,
                                           int R, int C, int ct, int rt, int z,
                                           float (*tile)[33])
{
    const size_t zoff = (size_t)z * R * C;
    const int r0 = rt * 64;
    const int c0 = ct * 32;
    const int tx = threadIdx.x & 31;
    const int ty = threadIdx.x >> 5;            // warp id 0..7

    const float* s = src + zoff + (size_t)r0 * C + c0;
    #pragma unroll
    for (int i = ty; i < 64; i += 8) tile[i][tx] = s[(size_t)i * C + tx];
    __syncthreads();

    __half* d = dst + zoff;
    #pragma unroll
    for (int j = 0; j < 4; j++) {
        const int c = ty + j * 8;               // column handled by this warp
        __half2 v = __floats2half2_rn(tile[2 * tx][c], tile[2 * tx + 1][c]);
        *(__half2*)(d + (size_t)(c0 + c) * R + r0 + 2 * tx) = v;
    }
}

__global__ void __launch_bounds__(256)
prep_kernel(const float* __restrict__ adj, __half* __restrict__ Jh,
            const float* __restrict__ x,   __half* __restrict__ XT,
            const float* __restrict__ W1,  __half* __restrict__ W1T,
            const float* __restrict__ W2,  __half* __restrict__ W2T,
            float* __restrict__ pool)
{
    __shared__ float tile[64][33];
    const int b = blockIdx.x;

    if (b < PREP_CVT_BLKS) {
        if (b == 0 && threadIdx.x < 64) pool[threadIdx.x] = 0.0f;
        const size_t n4 = (size_t)64 * 1024 * 1024 / 4;
        const size_t stride = (size_t)PREP_CVT_BLKS * 256;
        for (size_t i = (size_t)b * 256 + threadIdx.x; i < n4; i += stride) {
            float4 v = ((const float4*)adj)[i];
            uint2 o;
            o.x = pack2h(v.x, v.y);
            o.y = pack2h(v.z, v.w);
            ((uint2*)Jh)[i] = o;
        }
    } else if (b < PREP_CVT_BLKS + PREP_XT_BLKS) {
        const int t = b - PREP_CVT_BLKS;
        // x: R=1024 (16 rtiles), C=512 (16 ctiles), 64 batches
        trans_tile(x, XT, 1024, 512, t & 15, (t >> 4) & 15, t >> 8, tile);
    } else if (b < PREP_CVT_BLKS + PREP_XT_BLKS + PREP_W1_BLKS) {
        const int t = b - (PREP_CVT_BLKS + PREP_XT_BLKS);
        // W1: R=512 (8 rtiles), C=1024 (32 ctiles)
        trans_tile(W1, W1T, 512, 1024, t & 31, t >> 5, 0, tile);
    } else {
        const int t = b - (PREP_CVT_BLKS + PREP_XT_BLKS + PREP_W1_BLKS);
        // W2: R=1024 (16 rtiles), C=512 (16 ctiles)
        trans_tile(W2, W2T, 1024, 512, t & 15, t >> 4, 0, tile);
    }
}

// ---------------------------------------------------------------------------
// mma.sync fp16 GEMM: D[128,128] per CTA, 8 warps (2x4), warp tile 64x32.
// EPI: 0 = fp16 out; 1 = bias+ReLU fp16 out; 3 = bias+ReLU+masked pool.Wl.
// SWAP: blockIdx.x indexes M (keeps co-scheduled CTAs on the same B rows).
// ---------------------------------------------------------------------------
template <int EPI, bool SWAP>
__global__ void __launch_bounds__(256, 2)
mma_gemm(const __half* __restrict__ Ag, int lda, size_t strA,
         const __half* __restrict__ Bg, int ldb, size_t strB,
         const float* __restrict__ bias,
         __half* __restrict__ Ch, int ldc, size_t strC,
         const float* __restrict__ Wl, const int* __restrict__ length,
         float* __restrict__ pool,
         int nch)
{
    extern __shared__ char smem[];
    const int bz = blockIdx.z;
    const int m0 = (SWAP ? blockIdx.x : blockIdx.y) * BM;
    const int n0 = (SWAP ? blockIdx.y : blockIdx.x) * BN;

    int len = 0;
    if (EPI == 3) {
        len = length[bz];
        if (m0 >= len) return;
    }

    const uint32_t sb = smem_u32(smem);
    const int tid = threadIdx.x;
    const int wid = tid >> 5;
    const int l   = tid & 31;
    const int warp_m = wid & 1;    // 2 x 64 rows
    const int warp_n = wid >> 1;   // 4 x 32 cols

    const __half* pA = Ag + strA * bz;
    const __half* pB = Bg + strB * bz;

    const int ld_row = tid >> 3;
    const int ld_c16 = tid & 7;

    auto load_tiles = [&](int c, int st) {
        const int kbase = c * BK;
        const uint32_t sbase = sb + st * STG;
        #pragma unroll
        for (int it = 0; it < 4; it++) {
            const int row = ld_row + it * 32;
            cp16(sbase + SWZ((uint32_t)(row * 128 + ld_c16 * 16)),
                 pA + (size_t)(m0 + row) * lda + kbase + ld_c16 * 8);
        }
        #pragma unroll
        for (int it = 0; it < 4; it++) {
            const int row = ld_row + it * 32;
            cp16(sbase + A_BYTES + SWZ((uint32_t)(row * 128 + ld_c16 * 16)),
                 pB + (size_t)(n0 + row) * ldb + kbase + ld_c16 * 8);
        }
    };

    const int a_row_l = l & 15;
    const uint32_t a_koff = (uint32_t)((l >> 4) * 16);
    const int b_row_l = (l & 7) + ((l >> 4) * 8);
    const uint32_t b_koff = (uint32_t)(((l >> 3) & 1) * 16);

    uint32_t a_rb[4], b_rb[2];
    #pragma unroll
    for (int mi = 0; mi < 4; mi++)
        a_rb[mi] = (uint32_t)((warp_m * 64 + mi * 16 + a_row_l) * 128);
    #pragma unroll
    for (int nb = 0; nb < 2; nb++)
        b_rb[nb] = (uint32_t)((warp_n * 32 + nb * 16 + b_row_l) * 128);

    float acc[4][4][4];
    #pragma unroll
    for (int mi = 0; mi < 4; mi++)
        #pragma unroll
        for (int ni = 0; ni < 4; ni++)
            #pragma unroll
            for (int q = 0; q < 4; q++) acc[mi][ni][q] = 0.0f;

    load_tiles(0, 0);
    CP_COMMIT();
    if (1 < nch) { load_tiles(1, 1); CP_COMMIT(); }

    for (int c = 0; c < nch; c++) {
        if (c + 1 < nch) { CP_WAIT(1); } else { CP_WAIT(0); }
        __syncthreads();
        // Safe without a trailing barrier: stage (c+2)%3 == (c-1)%3, and every
        // warp consumed stage c-1 before it could reach the barrier above.
        if (c + 2 < nch) {
            load_tiles(c + 2, (c + 2) % NSTG);
            CP_COMMIT();
        }

        const uint32_t sA = sb + (c % NSTG) * STG;
        const uint32_t sB = sA + A_BYTES;

        #pragma unroll
        for (int ks = 0; ks < 4; ks++) {
            const uint32_t kb = (uint32_t)(ks * 32);
            uint32_t Ah[4][4], Bh[2][4];
            #pragma unroll
            for (int mi = 0; mi < 4; mi++)
                ldsm4(Ah[mi], sA + SWZ(a_rb[mi] + kb + a_koff));
            #pragma unroll
            for (int nb = 0; nb < 2; nb++)
                ldsm4(Bh[nb], sB + SWZ(b_rb[nb] + kb + b_koff));
            #pragma unroll
            for (int mi = 0; mi < 4; mi++)
                #pragma unroll
                for (int ni = 0; ni < 4; ni++)
                    mma_fp16(acc[mi][ni], Ah[mi], &Bh[ni >> 1][(ni & 1) * 2]);
        }
    }

    // ---- epilogue ----
    const int er = warp_m * 64 + (l >> 2);
    const int ec = warp_n * 32 + 2 * (l & 3);

    if (EPI <= 1) {
        #pragma unroll
        for (int mi = 0; mi < 4; mi++) {
            const int row = m0 + er + mi * 16;
            const size_t ro0 = strC * bz + (size_t)row * ldc;
            const size_t ro1 = ro0 + (size_t)8 * ldc;
            #pragma unroll
            for (int ni = 0; ni < 4; ni++) {
                const int col = n0 + ec + ni * 8;
                float v00 = acc[mi][ni][0], v01 = acc[mi][ni][1];
                float v10 = acc[mi][ni][2], v11 = acc[mi][ni][3];
                if (EPI == 1) {
                    const float2 bb = *(const float2*)(bias + col);
                    v00 = fmaxf(v00 + bb.x, 0.0f);
                    v01 = fmaxf(v01 + bb.y, 0.0f);
                    v10 = fmaxf(v10 + bb.x, 0.0f);
                    v11 = fmaxf(v11 + bb.y, 0.0f);
                }
                *(uint32_t*)(Ch + ro0 + col) = pack2h(v00, v01);
                *(uint32_t*)(Ch + ro1 + col) = pack2h(v10, v11);
            }
        }
    } else {
        // EPI==3: bias + ReLU + masked dot with Wl, reduce, atomicAdd per batch
        float part = 0.0f;
        #pragma unroll
        for (int mi = 0; mi < 4; mi++) {
            const int grow0 = m0 + er + mi * 16;
            const bool k0 = grow0 < len;
            const bool k1 = grow0 + 8 < len;
            #pragma unroll
            for (int ni = 0; ni < 4; ni++) {
                const int col = n0 + ec + ni * 8;
                const float2 bb = *(const float2*)(bias + col);
                const float2 wl = *(const float2*)(Wl + col);
                float v00 = fmaxf(acc[mi][ni][0] + bb.x, 0.0f);
                float v01 = fmaxf(acc[mi][ni][1] + bb.y, 0.0f);
                float v10 = fmaxf(acc[mi][ni][2] + bb.x, 0.0f);
                float v11 = fmaxf(acc[mi][ni][3] + bb.y, 0.0f);
                if (k0) part += v00 * wl.x + v01 * wl.y;
                if (k1) part += v10 * wl.x + v11 * wl.y;
            }
        }
        #pragma unroll
        for (int o = 16; o > 0; o >>= 1)
            part += __shfl_xor_sync(0xFFFFFFFFu, part, o);
        __syncthreads();
        float* red = (float*)smem;
        if (l == 0) red[wid] = part;
        __syncthreads();
        if (tid == 0) {
            float s = 0.0f;
            #pragma unroll
            for (int i = 0; i < 8; i++) s += red[i];
            atomicAdd(pool + bz, s);
        }
    }
}

// ---------------------------------------------------------------------------
__global__ void final_kernel(const float* __restrict__ pool,
                             const int* __restrict__ length,
                             const float* __restrict__ bl,
                             float* __restrict__ out)
{
    const int b = threadIdx.x;
    out[b] = pool[b] / (float)length[b] + bl[0];
}

// ---------------------------------------------------------------------------
extern "C" void kernel_launch(void* const* d_in, const int* in_sizes, int n_in,
                              void* d_out, int out_size)
{
    const float* x      = (const float*)d_in[0];
    const float* adj    = (const float*)d_in[1];
    const int*   length = (const int*)  d_in[2];
    const float* W1     = (const float*)d_in[3];
    const float* b1     = (const float*)d_in[4];
    const float* W2     = (const float*)d_in[5];
    const float* b2     = (const float*)d_in[6];
    const float* Wl     = (const float*)d_in[7];
    const float* bl     = (const float*)d_in[8];
    float* out = (float*)d_out;

    __half *Jh, *XT, *W1T, *W2T, *P1, *H1, *S2T;
    float* pool;
    cudaGetSymbolAddress((void**)&Jh,  g_Jh);
    cudaGetSymbolAddress((void**)&XT,  g_XT);
    cudaGetSymbolAddress((void**)&W1T, g_W1T);
    cudaGetSymbolAddress((void**)&W2T, g_W2T);
    cudaGetSymbolAddress((void**)&P1,  g_P1);
    cudaGetSymbolAddress((void**)&H1,  g_H1);
    cudaGetSymbolAddress((void**)&S2T, g_S2T);
    cudaGetSymbolAddress((void**)&pool, g_pool);

    cudaFuncSetAttribute(mma_gemm<0, false>, cudaFuncAttributeMaxDynamicSharedMemorySize, SMEM_TOTAL);
    cudaFuncSetAttribute(mma_gemm<1, false>, cudaFuncAttributeMaxDynamicSharedMemorySize, SMEM_TOTAL);
    cudaFuncSetAttribute(mma_gemm<0, true>,  cudaFuncAttributeMaxDynamicSharedMemorySize, SMEM_TOTAL);
    cudaFuncSetAttribute(mma_gemm<3, false>, cudaFuncAttributeMaxDynamicSharedMemorySize, SMEM_TOTAL);

    // Single prep launch: adj convert + x transpose + W transposes + pool zero
    prep_kernel<<<PREP_TOTAL, 256>>>(adj, Jh, x, XT, W1, W1T, W2, W2T, pool);

    // T1: P1[b] = adj[b] @ x[b]   (M=1024, N=512, K=1024) x64
    mma_gemm<0, false><<<dim3(4, 8, 64), 256, SMEM_TOTAL>>>(
        Jh, 1024, (size_t)1024 * 1024,
        XT, 1024, (size_t)512 * 1024,
        nullptr, P1, 512, (size_t)1024 * 512,
        nullptr, nullptr, nullptr, 1024 / BK);

    // T2: h1 = relu(P1 @ W1 + b1)  (M=65536, N=1024, K=512)
    mma_gemm<1, false><<<dim3(8, 512, 1), 256, SMEM_TOTAL>>>(
        P1, 512, 0,
        W1T, 512, 0,
        b1, H1, 1024, 0,
        nullptr, nullptr, nullptr, 512 / BK);

    // T3: S2^T = W2^T @ h1^T  (M=512, N=65536, K=1024), SWAP grid so the
    // co-scheduled M-blocks share each h1 row-group through L2.
    mma_gemm<0, true><<<dim3(4, 512, 1), 256, SMEM_TOTAL>>>(
        W2T, 1024, 0,
        H1, 1024, 0,
        nullptr, S2T, 65536, 0,
        nullptr, nullptr, nullptr, 1024 / BK);

    // T4: fused relu(adj[b]@S2[b]+b2) . Wl with row mask, row-block skip
    mma_gemm<3, false><<<dim3(4, 8, 64), 256, SMEM_TOTAL>>>(
        Jh, 1024, (size_t)1024 * 1024,
        S2T, 65536, 1024,
        b2, nullptr, 0, 0,
        Wl, length, pool, 1024 / BK);

    final_kernel<<<1, 64>>>(pool, length, bl, out);

    (void)in_sizes; (void)n_in; (void)out_size;
}